// round 2
// baseline (speedup 1.0000x reference)
#include <cuda_runtime.h>
#include <cstdint>
#include <math.h>

#define DIMS   128
#define BINSZ  500
#define KNE    5
#define TILE_R 64
#define TILE_C 64
#define MAXPTS 65536

// scratch (allocation-free rule: __device__ globals)
__device__ int   g_binid[MAXPTS];
__device__ float g_na[MAXPTS];
__device__ int   g_split[MAXPTS];

// ---------------------------------------------------------------------------
// K1: LSH projection -> bin id (first-max argmax) + squared norm per point
// ---------------------------------------------------------------------------
__global__ void proj_kernel(const float* __restrict__ pts,
                            const float* __restrict__ rot,
                            int total, int nbins, int rotcols)
{
    const int nproj = nbins >> 1;              // <= 8 here (5)
    __shared__ float s_rot[8 * DIMS];
    for (int i = threadIdx.x; i < nproj * DIMS; i += blockDim.x) {
        int h = i / DIMS, d = i - h * DIMS;
        s_rot[h * DIMS + d] = rot[d * rotcols + h];
    }
    __syncthreads();

    int p = blockIdx.x * blockDim.x + threadIdx.x;
    if (p >= total) return;

    const float4* pv = (const float4*)(pts + (size_t)p * DIMS);
    float m[8];
    #pragma unroll
    for (int h = 0; h < 8; h++) m[h] = 0.f;
    float nrm = 0.f;

    for (int d4 = 0; d4 < DIMS / 4; d4++) {
        float4 v = pv[d4];
        nrm += v.x * v.x + v.y * v.y + v.z * v.z + v.w * v.w;
        for (int h = 0; h < nproj; h++) {
            const float* r = &s_rot[h * DIMS + d4 * 4];
            m[h] += v.x * r[0] + v.y * r[1] + v.z * r[2] + v.w * r[3];
        }
    }

    // cmul = [m, -m]; first maximum wins (strict >)
    float best = m[0]; int bi = 0;
    for (int j = 1; j < nbins; j++) {
        float v = (j < nproj) ? m[j] : -m[j - nproj];
        if (v > best) { best = v; bi = j; }
    }
    g_binid[p] = bi;
    g_na[p]    = nrm;
}

// ---------------------------------------------------------------------------
// K2: stable counting sort of bin ids per batch == jnp.argsort (stable)
// One block per batch. Per-thread contiguous chunks keep stability.
// ---------------------------------------------------------------------------
__global__ void sort_kernel(int N, int nbins)
{
    const int T = 256;
    int b   = blockIdx.x;
    int tid = threadIdx.x;
    __shared__ int s_cnt[32 * T];     // nbins <= 32
    __shared__ int s_aux[9];

    int chunk = (N + T - 1) / T;
    int lo = tid * chunk; if (lo > N) lo = N;
    int hi = lo + chunk;  if (hi > N) hi = N;

    for (int bin = 0; bin < nbins; bin++) s_cnt[bin * T + tid] = 0;
    __syncthreads();
    for (int n = lo; n < hi; n++) s_cnt[g_binid[b * N + n] * T + tid]++;
    __syncthreads();

    // exclusive scan over (bin-major, thread-minor) order
    int run = 0;
    int lane = tid & 31, warp = tid >> 5;
    for (int bin = 0; bin < nbins; bin++) {
        int c = s_cnt[bin * T + tid];
        int x = c;
        #pragma unroll
        for (int o = 1; o < 32; o <<= 1) {
            int y = __shfl_up_sync(0xffffffffu, x, o);
            if (lane >= o) x += y;
        }
        if (lane == 31) s_aux[warp] = x;
        __syncthreads();
        if (warp == 0) {
            int w = (lane < 8) ? s_aux[lane] : 0;
            #pragma unroll
            for (int o = 1; o < 8; o <<= 1) {
                int y = __shfl_up_sync(0xffffffffu, w, o);
                if (lane >= o) w += y;
            }
            if (lane < 8) s_aux[lane] = w;
        }
        __syncthreads();
        int base = (warp > 0) ? s_aux[warp - 1] : 0;
        int ex   = base + x - c;          // exclusive within block
        int tot  = s_aux[7];              // block total
        __syncthreads();
        s_cnt[bin * T + tid] = run + ex;
        run += tot;
        __syncthreads();
    }

    // placement in original index order within each chunk -> stable
    for (int n = lo; n < hi; n++) {
        int bin = g_binid[b * N + n];
        int pos = s_cnt[bin * T + tid]++;
        g_split[b * N + pos] = n;
    }
}

// ---------------------------------------------------------------------------
// K3: per-bin gram + bottom-5-of-d2 selection (== top-5 of dm), scatter out.
// grid = (rowTiles=8, nbins, B); block = 256 = 16x16; thread tile = 4x4.
// dyn smem layout (bytes):
//   [0)      s_idx  500 int
//   [2048)   s_na   500 float
//   [4096)   s_rows float[128][64] (d-major, transposed)
//   [36864)  s_cols float[128][64]
//   merge overlay (post-compute): mk @4096 (64*16*5 f), mj @24576 (64*16*5 i)
// total 69632
// ---------------------------------------------------------------------------
__global__ void __launch_bounds__(256)
bin_kernel(const float* __restrict__ pts, float* __restrict__ out, int N)
{
    extern __shared__ char sm_raw[];
    int*   s_idx  = (int*)sm_raw;
    float* s_na   = (float*)(sm_raw + 2048);
    float* s_rows = (float*)(sm_raw + 4096);
    float* s_cols = (float*)(sm_raw + 36864);
    float* s_mk   = (float*)(sm_raw + 4096);
    int*   s_mj   = (int*)(sm_raw + 24576);

    int tile = blockIdx.x;
    int bin  = blockIdx.y;
    int b    = blockIdx.z;
    int tid  = threadIdx.x;
    int tx = tid & 15, ty = tid >> 4;

    for (int i = tid; i < BINSZ; i += 256) {
        int g = g_split[b * N + bin * BINSZ + i];
        s_idx[i] = g;
        s_na[i]  = g_na[b * N + g];
    }
    __syncthreads();

    // row tile (transposed, conflict-free stores: r = lane)
    int row0 = tile * TILE_R;
    for (int i = tid; i < TILE_R * (DIMS / 4); i += 256) {
        int r  = i & (TILE_R - 1);
        int d4 = i >> 6;
        float4 v = make_float4(0.f, 0.f, 0.f, 0.f);
        int grow = row0 + r;
        if (grow < BINSZ) {
            int g = s_idx[grow];
            v = ((const float4*)(pts + ((size_t)b * N + g) * DIMS))[d4];
        }
        s_rows[(d4 * 4 + 0) * TILE_R + r] = v.x;
        s_rows[(d4 * 4 + 1) * TILE_R + r] = v.y;
        s_rows[(d4 * 4 + 2) * TILE_R + r] = v.z;
        s_rows[(d4 * 4 + 3) * TILE_R + r] = v.w;
    }

    float na_row[4];
    float tk[4][5]; int tj[4][5];
    #pragma unroll
    for (int a = 0; a < 4; a++) {
        int grow = row0 + ty * 4 + a;
        na_row[a] = (grow < BINSZ) ? s_na[grow] : 0.f;
        #pragma unroll
        for (int q = 0; q < 5; q++) { tk[a][q] = 3.0e38f; tj[a][q] = 0x7fffffff; }
    }

    const int nchunks = (BINSZ + TILE_C - 1) / TILE_C;
    for (int c = 0; c < nchunks; c++) {
        __syncthreads();  // rows visible (1st iter) / cols of prev iter consumed
        for (int i = tid; i < TILE_C * (DIMS / 4); i += 256) {
            int j  = i & (TILE_C - 1);
            int d4 = i >> 6;
            int jloc = c * TILE_C + j;
            float4 v = make_float4(0.f, 0.f, 0.f, 0.f);
            if (jloc < BINSZ) {
                int g = s_idx[jloc];
                v = ((const float4*)(pts + ((size_t)b * N + g) * DIMS))[d4];
            }
            s_cols[(d4 * 4 + 0) * TILE_C + j] = v.x;
            s_cols[(d4 * 4 + 1) * TILE_C + j] = v.y;
            s_cols[(d4 * 4 + 2) * TILE_C + j] = v.z;
            s_cols[(d4 * 4 + 3) * TILE_C + j] = v.w;
        }
        __syncthreads();

        float acc[4][4];
        #pragma unroll
        for (int a = 0; a < 4; a++)
            #pragma unroll
            for (int q = 0; q < 4; q++) acc[a][q] = 0.f;

        #pragma unroll 4
        for (int d = 0; d < DIMS; d++) {
            float4 rv = *(const float4*)&s_rows[d * TILE_R + ty * 4];
            float4 cv = *(const float4*)&s_cols[d * TILE_C + tx * 4];
            acc[0][0] += rv.x * cv.x; acc[0][1] += rv.x * cv.y;
            acc[0][2] += rv.x * cv.z; acc[0][3] += rv.x * cv.w;
            acc[1][0] += rv.y * cv.x; acc[1][1] += rv.y * cv.y;
            acc[1][2] += rv.y * cv.z; acc[1][3] += rv.y * cv.w;
            acc[2][0] += rv.z * cv.x; acc[2][1] += rv.z * cv.y;
            acc[2][2] += rv.z * cv.z; acc[2][3] += rv.z * cv.w;
            acc[3][0] += rv.w * cv.x; acc[3][1] += rv.w * cv.y;
            acc[3][2] += rv.w * cv.z; acc[3][3] += rv.w * cv.w;
        }

        // candidates, j ascending per thread -> strict '<' keeps lowest index on ties
        #pragma unroll
        for (int q = 0; q < 4; q++) {
            int jloc = c * TILE_C + tx * 4 + q;
            if (jloc < BINSZ) {
                float ncol = s_na[jloc];
                #pragma unroll
                for (int a = 0; a < 4; a++) {
                    float key = fmaxf(na_row[a] - 2.f * acc[a][q] + ncol, 1e-6f);
                    if (key < tk[a][4]) {
                        tk[a][4] = key; tj[a][4] = jloc;
                        #pragma unroll
                        for (int p = 4; p > 0; p--) {
                            if (tk[a][p] < tk[a][p - 1]) {
                                float kt = tk[a][p]; tk[a][p] = tk[a][p - 1]; tk[a][p - 1] = kt;
                                int   jt = tj[a][p]; tj[a][p] = tj[a][p - 1]; tj[a][p - 1] = jt;
                            }
                        }
                    }
                }
            }
        }
    }

    __syncthreads();   // compute done; overlay merge buffers on rows/cols
    #pragma unroll
    for (int a = 0; a < 4; a++) {
        int r = ty * 4 + a;
        int base = (r * 16 + tx) * 5;
        #pragma unroll
        for (int q = 0; q < 5; q++) { s_mk[base + q] = tk[a][q]; s_mj[base + q] = tj[a][q]; }
    }
    __syncthreads();

    if (tid < TILE_R) {
        int r = tid;
        int grow = row0 + r;
        if (grow < BINSZ) {
            float fk[5]; int fj[5];
            #pragma unroll
            for (int q = 0; q < 5; q++) { fk[q] = 3.0e38f; fj[q] = 0x7fffffff; }
            for (int t = 0; t < 16; t++) {
                int base = (r * 16 + t) * 5;
                #pragma unroll
                for (int q = 0; q < 5; q++) {
                    float key = s_mk[base + q]; int j = s_mj[base + q];
                    bool better = (key < fk[4]) || (key == fk[4] && j < fj[4]);
                    if (better) {
                        fk[4] = key; fj[4] = j;
                        #pragma unroll
                        for (int p = 4; p > 0; p--) {
                            bool sw = (fk[p] < fk[p - 1]) ||
                                      (fk[p] == fk[p - 1] && fj[p] < fj[p - 1]);
                            if (sw) {
                                float kt = fk[p]; fk[p] = fk[p - 1]; fk[p - 1] = kt;
                                int   jt = fj[p]; fj[p] = fj[p - 1]; fj[p - 1] = jt;
                            }
                        }
                    }
                }
            }
            int src = s_idx[grow];
            size_t rowbase = ((size_t)b * N + src) * (size_t)N;
            #pragma unroll
            for (int q = 0; q < 5; q++) {
                float val = expf(-0.1f * sqrtf(fk[q]));   // only 5 per row survive
                out[rowbase + (size_t)s_idx[fj[q]]] = val; // unique (src,dst): plain store
            }
        }
    }
}

// ---------------------------------------------------------------------------
extern "C" void kernel_launch(void* const* d_in, const int* in_sizes, int n_in,
                              void* d_out, int out_size)
{
    const float* pts = (const float*)d_in[0];
    const float* rot = (const float*)d_in[1];

    int P       = in_sizes[0] / DIMS;                 // B*N
    int rotcols = in_sizes[1] / DIMS;                 // MAX_NUM_BINS/2
    int N       = (int)((long long)out_size / P);     // out = B*N*N
    int nbins   = N / BINSZ;

    cudaMemsetAsync(d_out, 0, (size_t)out_size * sizeof(float));

    proj_kernel<<<(P + 255) / 256, 256>>>(pts, rot, P, nbins, rotcols);
    sort_kernel<<<(P / N), 256>>>(N, nbins);

    const int smem_bytes = 69632;
    cudaFuncSetAttribute(bin_kernel, cudaFuncAttributeMaxDynamicSharedMemorySize, smem_bytes);
    int ntiles = (BINSZ + TILE_R - 1) / TILE_R;
    dim3 grid(ntiles, nbins, (P / N));
    bin_kernel<<<grid, 256, smem_bytes>>>(pts, (float*)d_out, N);
}